// round 8
// baseline (speedup 1.0000x reference)
#include <cuda_runtime.h>
#include <cuda_bf16.h>
#include <cstdint>

#define NN 8192
#define FI 128
#define FO 64
#define LRALPHA 0.2f
#define KSPLIT 4
#define MT 128          // M rows per CTA
#define KT 64           // j per K-tile
#define NB 72           // padded N (64 feat + 1 den + 7 pad)
#define STRIDE_OUT 72

// ---------------- device scratch ----------------
__device__ float g_h[NN*FO];
__device__ __align__(16) float g_t[NN];
__device__ __align__(16) float g_u[NN], g_v[NN];       // fp32 exp(t), exp(a t)
__device__ float g_s[NN], g_p[NN], g_q[NN];
__device__ __align__(16) __nv_bfloat16 g_Bh[(size_t)NB*NN];  // bf16(h | 1)
__device__ __align__(16) __nv_bfloat16 g_Bl[(size_t)NB*NN];  // residual
__device__ float g_num[KSPLIT][(size_t)NN*STRIDE_OUT];

// ---------------- helpers ----------------
__device__ __forceinline__ uint32_t smem_u32(const void* p) {
    uint32_t a;
    asm("{ .reg .u64 t; cvta.to.shared.u64 t, %1; cvt.u32.u64 %0, t; }" : "=r"(a) : "l"(p));
    return a;
}
#define SWZ(x) ((uint32_t)(x) ^ ((((uint32_t)(x)) >> 3) & 0x70u))

__device__ __forceinline__ void ldm_x4(uint32_t addr, uint32_t r[4]) {
    asm volatile("ldmatrix.sync.aligned.m8n8.x4.shared.b16 {%0,%1,%2,%3}, [%4];"
        : "=r"(r[0]), "=r"(r[1]), "=r"(r[2]), "=r"(r[3]) : "r"(addr));
}
__device__ __forceinline__ void ldm_x2(uint32_t addr, uint32_t r[2]) {
    asm volatile("ldmatrix.sync.aligned.m8n8.x2.shared.b16 {%0,%1}, [%2];"
        : "=r"(r[0]), "=r"(r[1]) : "r"(addr));
}
__device__ __forceinline__ void mma16816(float* c, const uint32_t* a, const uint32_t* b) {
    asm("mma.sync.aligned.m16n8k16.row.col.f32.bf16.bf16.f32 "
        "{%0,%1,%2,%3}, {%4,%5,%6,%7}, {%8,%9}, {%0,%1,%2,%3};"
        : "+f"(c[0]), "+f"(c[1]), "+f"(c[2]), "+f"(c[3])
        : "r"(a[0]), "r"(a[1]), "r"(a[2]), "r"(a[3]), "r"(b[0]), "r"(b[1]));
}
__device__ __forceinline__ void cp16(uint32_t dst, const void* src) {
    asm volatile("cp.async.cg.shared.global [%0], [%1], 16;" :: "r"(dst), "l"(src) : "memory");
}
#define CP_COMMIT() asm volatile("cp.async.commit_group;" ::: "memory")
#define CP_WAIT(n)  asm volatile("cp.async.wait_group %0;" :: "n"(n) : "memory")
__device__ __forceinline__ void prefetchL1(const void* p) {
    asm volatile("prefetch.global.L1 [%0];" :: "l"(p));
}

// build one hi/lo fragment u32 pair from 2 edges
__device__ __forceinline__ void makefrag(uint32_t& hi, uint32_t& lo,
        int2 e, float2 tt, float2 uu, float2 vv, float p, float q, float ns) {
    float w0 = 0.f, w1 = 0.f;
    if (e.x > 0) w0 = (tt.x > ns) ? p * uu.x : q * vv.x;
    if (e.y > 0) w1 = (tt.y > ns) ? p * uu.y : q * vv.y;
    uint32_t b0 = __float_as_uint(w0), b1 = __float_as_uint(w1);
    hi = __byte_perm(b0, b1, 0x7632);
    float h0 = __uint_as_float(b0 & 0xFFFF0000u);
    float h1 = __uint_as_float(b1 & 0xFFFF0000u);
    lo = __byte_perm(__float_as_uint(w0 - h0), __float_as_uint(w1 - h1), 0x7632);
}

// ---------------- kernel 1: h = x @ W  (+ fused per-row scalars) ----------------
__global__ void k_gemm_h(const float* __restrict__ x, const float* __restrict__ W,
                         const float* __restrict__ a) {
    __shared__ float sW[FI*FO];     // reused as sh[64][64]
    __shared__ float sx[64][FI];
    int tid = threadIdx.x;
    for (int i = tid; i < FI*FO; i += 256) sW[i] = W[i];
    int r0 = blockIdx.x * 64;
    for (int i = tid; i < 64*FI; i += 256)
        sx[i >> 7][i & 127] = x[(size_t)(r0 + (i >> 7))*FI + (i & 127)];
    __syncthreads();
    int col = tid & 63;
    float accv[16];
    int cnt = 0;
    for (int rr = tid >> 6; rr < 64; rr += 4) {
        float acc = 0.f;
        #pragma unroll
        for (int k = 0; k < FI; k++) acc += sx[rr][k] * sW[k*FO + col];
        g_h[(size_t)(r0 + rr)*FO + col] = acc;
        accv[cnt++] = acc;
    }
    __syncthreads();
    float* sh = sW;
    cnt = 0;
    for (int rr = tid >> 6; rr < 64; rr += 4) sh[rr*64 + col] = accv[cnt++];
    __syncthreads();
    int w = tid >> 5, lane = tid & 31;
    for (int rr = w * 8; rr < w * 8 + 8; rr++) {
        float h0 = sh[rr*64 + lane];
        float h1 = sh[rr*64 + 32 + lane];
        float s = h0 * a[lane]      + h1 * a[lane + 32];
        float t = h0 * a[lane + 64] + h1 * a[lane + 96];
        #pragma unroll
        for (int o = 16; o; o >>= 1) {
            s += __shfl_xor_sync(0xffffffffu, s, o);
            t += __shfl_xor_sync(0xffffffffu, t, o);
        }
        if (lane == 0) {
            int gi = r0 + rr;
            g_s[gi] = s; g_t[gi] = t;
            g_p[gi] = expf(s); g_q[gi] = expf(LRALPHA * s);
            g_u[gi] = expf(t); g_v[gi] = expf(LRALPHA * t);
        }
    }
}

// -------- kernel 2: bf16 hi/lo split of [h | 1 | 0pad], N-major --------
__global__ void k_tables() {
    int n = blockIdx.y;
    int j = blockIdx.x * 256 + threadIdx.x;
    float base;
    if (n < FO)       base = g_h[(size_t)j*FO + n];
    else if (n == FO) base = 1.f;
    else              base = 0.f;
    __nv_bfloat16 bh = __float2bfloat16(base);
    size_t o = (size_t)n*NN + j;
    g_Bh[o] = bh;
    g_Bl[o] = __float2bfloat16(base - __bfloat162float(bh));
}

// ---------------- kernel 3: merged-branch HMMA masked GEMM ----------------
// SMEM: B ring, 3 stages x 2 streams x 9216 = 55296
#define B_BYTES  (NB*128)                    // 9216
#define BSTG     (2*B_BYTES)                 // 18432
#define SM_TOTAL (3*BSTG)                    // 55296

__global__ void __launch_bounds__(256, 2) k_main_tc(const int* __restrict__ adj) {
    extern __shared__ char smem[];
    uint32_t sb = smem_u32(smem);
    int tid = threadIdx.x, w = tid >> 5, lane = tid & 31;
    int wm = w & 3, wn = w >> 2;                 // 4 M-groups x 2 N-groups
    int gp = lane >> 2, tg = lane & 3;
    int i0 = blockIdx.x * MT;
    int sp = blockIdx.y;
    int jbase = sp * (NN / KSPLIT);
    const int nTiles = (NN / KSPLIT) / KT;       // 32

    // 4 rows per thread: mt*16 + rr*8 + gp within warp's 32-row band
    float negs[4], pv[4], qv[4];
    const int* adjRow[4];
    #pragma unroll
    for (int rx = 0; rx < 4; rx++) {
        int r = i0 + wm * 32 + (rx >> 1) * 16 + (rx & 1) * 8 + gp;
        negs[rx] = -g_s[r];
        pv[rx]   = g_p[r];
        qv[rx]   = g_q[r];
        adjRow[rx] = adj + (size_t)r * NN;
    }

    float acc[2][5][4];
    #pragma unroll
    for (int mt = 0; mt < 2; mt++)
        #pragma unroll
        for (int nb = 0; nb < 5; nb++)
            #pragma unroll
            for (int e = 0; e < 4; e++) acc[mt][nb][e] = 0.f;

    int nbBase = wn * 4;
    uint32_t bByte   = (uint32_t)(lane & 7) * 128 + ((lane >> 3) & 1) * 16
                     + ((lane >> 4) & 1) * 1024;
    uint32_t bByteX2 = (uint32_t)(lane & 7) * 128 + ((lane >> 3) & 1) * 16;

    auto prefetchB = [&](int tt, int st) {
        int j0 = jbase + tt * KT;
        uint32_t bdst = sb + st * BSTG;
        for (int v = tid; v < NB * 8; v += 256) {
            int n = v >> 3, ch = v & 7;
            uint32_t so = SWZ((uint32_t)(n * 128 + ch * 16));
            size_t src = (size_t)n * NN + j0 + ch * 8;
            cp16(bdst + so,           g_Bh + src);
            cp16(bdst + B_BYTES + so, g_Bl + src);
        }
    };

    prefetchB(0, 0); CP_COMMIT();
    prefetchB(1, 1); CP_COMMIT();

    for (int t = 0; t < nTiles; t++) {
        int st = t % 3;
        int j0 = jbase + t * KT;
        CP_WAIT(1);
        __syncthreads();     // stage st ready; stage (t+2)%3 free (its readers done)
        if (t + 2 < nTiles) prefetchB(t + 2, (t + 2) % 3);
        CP_COMMIT();         // unconditional: keeps wait_group accounting uniform
        if (t + 1 < nTiles)
            prefetchL1(adj + (size_t)(i0 + (tid >> 1)) * NN + (j0 + KT) + (tid & 1) * 32);

        uint32_t bbase = sb + st * BSTG;
        #pragma unroll
        for (int ks = 0; ks < 4; ks++) {
            int jc = j0 + ks * 16 + 2 * tg;
            float2 tA = *(const float2*)(g_t + jc);
            float2 tB = *(const float2*)(g_t + jc + 8);
            float2 uA = *(const float2*)(g_u + jc);
            float2 uB = *(const float2*)(g_u + jc + 8);
            float2 vA = *(const float2*)(g_v + jc);
            float2 vB = *(const float2*)(g_v + jc + 8);

            // build A fragments directly in registers
            uint32_t aHi[2][4], aLo[2][4];
            #pragma unroll
            for (int mt = 0; mt < 2; mt++) {
                #pragma unroll
                for (int rr = 0; rr < 2; rr++) {
                    int rx = mt * 2 + rr;
                    int2 eA = *(const int2*)(adjRow[rx] + jc);
                    int2 eB = *(const int2*)(adjRow[rx] + jc + 8);
                    makefrag(aHi[mt][rr],     aLo[mt][rr],
                             eA, tA, uA, vA, pv[rx], qv[rx], negs[rx]);
                    makefrag(aHi[mt][rr + 2], aLo[mt][rr + 2],
                             eB, tB, uB, vB, pv[rx], qv[rx], negs[rx]);
                }
            }

            uint32_t kB = (uint32_t)ks * 32;
            #pragma unroll
            for (int pr = 0; pr < 2; pr++) {
                uint32_t boff = SWZ(bByte + (nbBase + 2 * pr) * 1024u + kB);
                uint32_t bh[4], bl[4];
                ldm_x4(bbase + boff, bh);
                ldm_x4(bbase + B_BYTES + boff, bl);
                mma16816(acc[0][2*pr],   aHi[0], bh);
                mma16816(acc[1][2*pr],   aHi[1], bh);
                mma16816(acc[0][2*pr+1], aHi[0], bh + 2);
                mma16816(acc[1][2*pr+1], aHi[1], bh + 2);
                mma16816(acc[0][2*pr],   aLo[0], bh);
                mma16816(acc[1][2*pr],   aLo[1], bh);
                mma16816(acc[0][2*pr+1], aLo[0], bh + 2);
                mma16816(acc[1][2*pr+1], aLo[1], bh + 2);
                mma16816(acc[0][2*pr],   aHi[0], bl);
                mma16816(acc[1][2*pr],   aHi[1], bl);
                mma16816(acc[0][2*pr+1], aHi[0], bl + 2);
                mma16816(acc[1][2*pr+1], aHi[1], bl + 2);
            }
            if (wn == 1) {     // block 8 (denominator col) via x2
                uint32_t boff = SWZ(bByteX2 + 8192u + kB);
                uint32_t bh2[2], bl2[2];
                ldm_x2(bbase + boff, bh2);
                ldm_x2(bbase + B_BYTES + boff, bl2);
                mma16816(acc[0][4], aHi[0], bh2);
                mma16816(acc[1][4], aHi[1], bh2);
                mma16816(acc[0][4], aLo[0], bh2);
                mma16816(acc[1][4], aLo[1], bh2);
                mma16816(acc[0][4], aHi[0], bl2);
                mma16816(acc[1][4], aHi[1], bl2);
            }
        }
    }

    // ---- epilogue: write fp32 partials ----
    int nBlk = 4 + wn;
    #pragma unroll
    for (int mt = 0; mt < 2; mt++) {
        int row0 = i0 + wm * 32 + mt * 16 + gp;
        for (int nb = 0; nb < nBlk; nb++) {
            int col = (nbBase + nb) * 8 + tg * 2;
            size_t o0 = (size_t)row0 * STRIDE_OUT + col;
            size_t o1 = (size_t)(row0 + 8) * STRIDE_OUT + col;
            g_num[sp][o0]     = acc[mt][nb][0];
            g_num[sp][o0 + 1] = acc[mt][nb][1];
            g_num[sp][o1]     = acc[mt][nb][2];
            g_num[sp][o1 + 1] = acc[mt][nb][3];
        }
    }
}

// ---------------- kernel 4: combine splits, divide, ELU ----------------
__global__ void k_final(float* __restrict__ out) {
    int idx = blockIdx.x * 256 + threadIdx.x;
    int i = idx >> 6, c = idx & 63;
    size_t b = (size_t)i * STRIDE_OUT;
    float num = 0.f, den = 0.f;
    #pragma unroll
    for (int s2 = 0; s2 < KSPLIT; s2++) {
        num += g_num[s2][b + c];
        den += g_num[s2][b + 64];
    }
    float hv = num / den;
    out[idx] = hv > 0.f ? hv : expm1f(hv);
}

extern "C" void kernel_launch(void* const* d_in, const int* in_sizes, int n_in,
                              void* d_out, int out_size) {
    const float* x   = (const float*)d_in[0];
    const int*   adj = (const int*)  d_in[1];
    const float* W   = (const float*)d_in[2];
    const float* a   = (const float*)d_in[3];
    float* out = (float*)d_out;

    cudaFuncSetAttribute(k_main_tc, cudaFuncAttributeMaxDynamicSharedMemorySize, SM_TOTAL);

    k_gemm_h<<<NN/64, 256>>>(x, W, a);
    dim3 gt(NN/256, NB);
    k_tables<<<gt, 256>>>();
    dim3 gm(NN/MT, KSPLIT);
    k_main_tc<<<gm, 256, SM_TOTAL>>>(adj);
    k_final<<<(NN*FO)/256, 256>>>(out);
}

// round 9
// speedup vs baseline: 1.3461x; 1.3461x over previous
#include <cuda_runtime.h>
#include <cuda_bf16.h>
#include <cstdint>

#define NN 8192
#define FI 128
#define FO 64
#define LRALPHA 0.2f
#define KSPLIT 4
#define MT 128          // M rows per CTA
#define KT 64           // j per K-tile
#define NB 72           // padded N (64 feat + 1 den + 7 pad)
#define STRIDE_OUT 72

// ---------------- device scratch ----------------
__device__ float g_h[NN*FO];
__device__ __align__(16) float g_t[NN];
__device__ __align__(16) float g_u[NN], g_v[NN];   // fp32 exp(t), exp(a t)
__device__ float g_s[NN], g_p[NN], g_q[NN];
__device__ __align__(16) __nv_bfloat16 g_Bh[(size_t)NB*NN];  // bf16(h | 1)
__device__ __align__(16) __nv_bfloat16 g_Bl[(size_t)NB*NN];  // residual
__device__ float g_num[KSPLIT][(size_t)NN*STRIDE_OUT];

// ---------------- helpers ----------------
__device__ __forceinline__ uint32_t smem_u32(const void* p) {
    uint32_t a;
    asm("{ .reg .u64 t; cvta.to.shared.u64 t, %1; cvt.u32.u64 %0, t; }" : "=r"(a) : "l"(p));
    return a;
}
#define SWZ(x) ((uint32_t)(x) ^ ((((uint32_t)(x)) >> 3) & 0x70u))

__device__ __forceinline__ void ldm_x4(uint32_t addr, uint32_t r[4]) {
    asm volatile("ldmatrix.sync.aligned.m8n8.x4.shared.b16 {%0,%1,%2,%3}, [%4];"
        : "=r"(r[0]), "=r"(r[1]), "=r"(r[2]), "=r"(r[3]) : "r"(addr));
}
__device__ __forceinline__ void ldm_x2(uint32_t addr, uint32_t r[2]) {
    asm volatile("ldmatrix.sync.aligned.m8n8.x2.shared.b16 {%0,%1}, [%2];"
        : "=r"(r[0]), "=r"(r[1]) : "r"(addr));
}
__device__ __forceinline__ void mma16816(float* c, const uint32_t* a, const uint32_t* b) {
    asm("mma.sync.aligned.m16n8k16.row.col.f32.bf16.bf16.f32 "
        "{%0,%1,%2,%3}, {%4,%5,%6,%7}, {%8,%9}, {%0,%1,%2,%3};"
        : "+f"(c[0]), "+f"(c[1]), "+f"(c[2]), "+f"(c[3])
        : "r"(a[0]), "r"(a[1]), "r"(a[2]), "r"(a[3]), "r"(b[0]), "r"(b[1]));
}
__device__ __forceinline__ void cp16(uint32_t dst, const void* src) {
    asm volatile("cp.async.cg.shared.global [%0], [%1], 16;" :: "r"(dst), "l"(src) : "memory");
}
#define CP_COMMIT() asm volatile("cp.async.commit_group;" ::: "memory")
#define CP_WAIT(n)  asm volatile("cp.async.wait_group %0;" :: "n"(n) : "memory")
__device__ __forceinline__ void prefetchL1(const void* p) {
    asm volatile("prefetch.global.L1 [%0];" :: "l"(p));
}

// pack two fp32 weights into hi-bf16x2 and lo-bf16x2 (truncation split)
__device__ __forceinline__ void packpair(uint32_t& hi, uint32_t& lo, float w0, float w1) {
    uint32_t b0 = __float_as_uint(w0), b1 = __float_as_uint(w1);
    hi = __byte_perm(b0, b1, 0x7632);
    float l0 = w0 - __uint_as_float(b0 & 0xFFFF0000u);
    float l1 = w1 - __uint_as_float(b1 & 0xFFFF0000u);
    lo = __byte_perm(__float_as_uint(l0), __float_as_uint(l1), 0x7632);
}

// ---------------- kernel 1: h = x @ W  (+ fused per-row scalars) ----------------
__global__ void k_gemm_h(const float* __restrict__ x, const float* __restrict__ W,
                         const float* __restrict__ a) {
    __shared__ float sW[FI*FO];     // reused as sh[64][64]
    __shared__ float sx[64][FI];
    int tid = threadIdx.x;
    for (int i = tid; i < FI*FO; i += 256) sW[i] = W[i];
    int r0 = blockIdx.x * 64;
    for (int i = tid; i < 64*FI; i += 256)
        sx[i >> 7][i & 127] = x[(size_t)(r0 + (i >> 7))*FI + (i & 127)];
    __syncthreads();
    int col = tid & 63;
    float accv[16];
    int cnt = 0;
    for (int rr = tid >> 6; rr < 64; rr += 4) {
        float acc = 0.f;
        #pragma unroll
        for (int k = 0; k < FI; k++) acc += sx[rr][k] * sW[k*FO + col];
        g_h[(size_t)(r0 + rr)*FO + col] = acc;
        accv[cnt++] = acc;
    }
    __syncthreads();
    float* sh = sW;
    cnt = 0;
    for (int rr = tid >> 6; rr < 64; rr += 4) sh[rr*64 + col] = accv[cnt++];
    __syncthreads();
    int w = tid >> 5, lane = tid & 31;
    for (int rr = w * 8; rr < w * 8 + 8; rr++) {
        float h0 = sh[rr*64 + lane];
        float h1 = sh[rr*64 + 32 + lane];
        float s = h0 * a[lane]      + h1 * a[lane + 32];
        float t = h0 * a[lane + 64] + h1 * a[lane + 96];
        #pragma unroll
        for (int o = 16; o; o >>= 1) {
            s += __shfl_xor_sync(0xffffffffu, s, o);
            t += __shfl_xor_sync(0xffffffffu, t, o);
        }
        if (lane == 0) {
            int gi = r0 + rr;
            g_s[gi] = s; g_t[gi] = t;
            g_p[gi] = expf(s); g_q[gi] = expf(LRALPHA * s);
            g_u[gi] = expf(t); g_v[gi] = expf(LRALPHA * t);
        }
    }
}

// -------- kernel 2: bf16 hi/lo split of [h | 1 | 0pad], N-major --------
__global__ void k_tables() {
    int n = blockIdx.y;
    int j = blockIdx.x * 256 + threadIdx.x;
    float base;
    if (n < FO)       base = g_h[(size_t)j*FO + n];
    else if (n == FO) base = 1.f;
    else              base = 0.f;
    __nv_bfloat16 bh = __float2bfloat16(base);
    size_t o = (size_t)n*NN + j;
    g_Bh[o] = bh;
    g_Bl[o] = __float2bfloat16(base - __bfloat162float(bh));
}

// ---------------- kernel 3: merged-branch HMMA masked GEMM ----------------
// SMEM: s/p/q 1.5K(pad 2K) | WH 16K | WL 16K | B 2 stages x 2 streams x 9216
#define SM_SS    0
#define SM_WH    2048
#define A_BYTES  (MT*128)                    // 16384
#define SM_WL    (SM_WH + A_BYTES)
#define SM_B     (SM_WL + A_BYTES)           // 34816
#define B_BYTES  (NB*128)                    // 9216
#define BSTG     (2*B_BYTES)                 // 18432
#define SM_TOTAL (SM_B + 2*BSTG)             // 71680

__global__ void __launch_bounds__(256, 2) k_main_tc(const int* __restrict__ adj) {
    extern __shared__ char smem[];
    uint32_t sb = smem_u32(smem);
    int tid = threadIdx.x, w = tid >> 5, lane = tid & 31;
    int wm = w & 3, wn = w >> 2;                 // 4 M-groups x 2 N-groups
    int i0 = blockIdx.x * MT;
    int sp = blockIdx.y;
    int jbase = sp * (NN / KSPLIT);
    const int nTiles = (NN / KSPLIT) / KT;       // 32

    float* s_s = (float*)(smem + SM_SS);         // [128]
    float* s_p = s_s + 128;                      // [128]
    float* s_q = s_s + 256;                      // [128]
    if (tid < MT) {
        s_s[tid] = g_s[i0 + tid];
        s_p[tid] = g_p[i0 + tid];
        s_q[tid] = g_q[i0 + tid];
    }

    float acc[2][5][4];
    #pragma unroll
    for (int mt = 0; mt < 2; mt++)
        #pragma unroll
        for (int nb = 0; nb < 5; nb++)
            #pragma unroll
            for (int e = 0; e < 4; e++) acc[mt][nb][e] = 0.f;

    int nbBase = wn * 4;
    uint32_t aRowByte = (uint32_t)(wm * 32 + (lane & 15)) * 128;
    uint32_t aKHalf   = ((lane >> 4) & 1) * 16;
    uint32_t bByte    = (uint32_t)(lane & 7) * 128 + ((lane >> 3) & 1) * 16
                      + ((lane >> 4) & 1) * 1024;
    uint32_t bByteX2  = (uint32_t)(lane & 7) * 128 + ((lane >> 3) & 1) * 16;

    auto prefetchB = [&](int tt, int st) {
        int j0 = jbase + tt * KT;
        uint32_t bdst = sb + SM_B + st * BSTG;
        for (int v = tid; v < NB * 8; v += 256) {
            int n = v >> 3, ch = v & 7;
            uint32_t so = SWZ((uint32_t)(n * 128 + ch * 16));
            size_t src = (size_t)n * NN + j0 + ch * 8;
            cp16(bdst + so,           g_Bh + src);
            cp16(bdst + B_BYTES + so, g_Bl + src);
        }
    };

    prefetchB(0, 0);
    CP_COMMIT();

    for (int t = 0; t < nTiles; t++) {
        int st = t & 1;
        int j0 = jbase + t * KT;
        __syncthreads();     // prior MMA done reading W tiles and B stage (1-st)

        // ---- build fp32-weight hi/lo bf16 tiles W (128 x 64, SW128) ----
        #pragma unroll
        for (int it = 0; it < 4; it++) {
            int idx = it * 256 + tid;            // 0..1023; 8 edges each
            int r = idx >> 3, seg = idx & 7;
            const int* ap = adj + (size_t)(i0 + r) * NN + j0 + seg * 8;
            int4 a0 = __ldg((const int4*)ap);
            int4 a1 = __ldg((const int4*)(ap + 4));
            const float* tp = g_t + j0 + seg * 8;
            float4 t0 = *(const float4*)tp;
            float4 t1 = *(const float4*)(tp + 4);
            float4 u0 = *(const float4*)(g_u + j0 + seg * 8);
            float4 u1 = *(const float4*)(g_u + j0 + seg * 8 + 4);
            float4 v0 = *(const float4*)(g_v + j0 + seg * 8);
            float4 v1 = *(const float4*)(g_v + j0 + seg * 8 + 4);
            float sr = s_s[r], pr_ = s_p[r], qr_ = s_q[r];
            float w0 = (a0.x > 0) ? ((sr + t0.x > 0.f) ? pr_ * u0.x : qr_ * v0.x) : 0.f;
            float w1 = (a0.y > 0) ? ((sr + t0.y > 0.f) ? pr_ * u0.y : qr_ * v0.y) : 0.f;
            float w2 = (a0.z > 0) ? ((sr + t0.z > 0.f) ? pr_ * u0.z : qr_ * v0.z) : 0.f;
            float w3 = (a0.w > 0) ? ((sr + t0.w > 0.f) ? pr_ * u0.w : qr_ * v0.w) : 0.f;
            float w4 = (a1.x > 0) ? ((sr + t1.x > 0.f) ? pr_ * u1.x : qr_ * v1.x) : 0.f;
            float w5 = (a1.y > 0) ? ((sr + t1.y > 0.f) ? pr_ * u1.y : qr_ * v1.y) : 0.f;
            float w6 = (a1.z > 0) ? ((sr + t1.z > 0.f) ? pr_ * u1.z : qr_ * v1.z) : 0.f;
            float w7 = (a1.w > 0) ? ((sr + t1.w > 0.f) ? pr_ * u1.w : qr_ * v1.w) : 0.f;
            uint4 H, L;
            packpair(H.x, L.x, w0, w1);
            packpair(H.y, L.y, w2, w3);
            packpair(H.z, L.z, w4, w5);
            packpair(H.w, L.w, w6, w7);
            uint32_t boff = SWZ((uint32_t)(r * 128 + seg * 16));
            *(uint4*)(smem + SM_WH + boff) = H;
            *(uint4*)(smem + SM_WL + boff) = L;
        }

        if (t + 1 < nTiles) {
            prefetchB(t + 1, 1 - st);
            CP_COMMIT();
            CP_WAIT(1);
        } else {
            CP_WAIT(0);
        }
        __syncthreads();

        // prefetch next tile's adj into L1 (one 128B line per thread)
        if (t + 1 < nTiles)
            prefetchL1(adj + (size_t)(i0 + (tid >> 1)) * NN + (j0 + KT) + (tid & 1) * 32);

        // ---- MMA phase: 4 ksteps ----
        uint32_t bbase = sb + SM_B + st * BSTG;
        #pragma unroll
        for (int ks = 0; ks < 4; ks++) {
            uint32_t kB = (uint32_t)ks * 32;
            uint32_t aH[2][4], aL[2][4];
            #pragma unroll
            for (int mt = 0; mt < 2; mt++) {
                uint32_t aoff = SWZ(aRowByte + mt * 2048u + kB + aKHalf);
                ldm_x4(sb + SM_WH + aoff, aH[mt]);
                ldm_x4(sb + SM_WL + aoff, aL[mt]);
            }
            #pragma unroll
            for (int pr = 0; pr < 2; pr++) {
                uint32_t boff = SWZ(bByte + (nbBase + 2 * pr) * 1024u + kB);
                uint32_t bh[4], bl[4];
                ldm_x4(bbase + boff, bh);
                ldm_x4(bbase + B_BYTES + boff, bl);
                mma16816(acc[0][2*pr],   aH[0], bh);
                mma16816(acc[1][2*pr],   aH[1], bh);
                mma16816(acc[0][2*pr+1], aH[0], bh + 2);
                mma16816(acc[1][2*pr+1], aH[1], bh + 2);
                mma16816(acc[0][2*pr],   aL[0], bh);
                mma16816(acc[1][2*pr],   aL[1], bh);
                mma16816(acc[0][2*pr+1], aL[0], bh + 2);
                mma16816(acc[1][2*pr+1], aL[1], bh + 2);
                mma16816(acc[0][2*pr],   aH[0], bl);
                mma16816(acc[1][2*pr],   aH[1], bl);
                mma16816(acc[0][2*pr+1], aH[0], bl + 2);
                mma16816(acc[1][2*pr+1], aH[1], bl + 2);
            }
            if (wn == 1) {     // block 8 (denominator col) via x2
                uint32_t boff = SWZ(bByteX2 + 8192u + kB);
                uint32_t bh2[2], bl2[2];
                ldm_x2(bbase + boff, bh2);
                ldm_x2(bbase + B_BYTES + boff, bl2);
                mma16816(acc[0][4], aH[0], bh2);
                mma16816(acc[1][4], aH[1], bh2);
                mma16816(acc[0][4], aL[0], bh2);
                mma16816(acc[1][4], aL[1], bh2);
                mma16816(acc[0][4], aH[0], bl2);
                mma16816(acc[1][4], aH[1], bl2);
            }
        }
    }

    // ---- epilogue: write fp32 partials (p/q already folded in) ----
    int gp = lane >> 2, tg = lane & 3;
    int nBlk = 4 + wn;
    #pragma unroll
    for (int mt = 0; mt < 2; mt++) {
        int row0 = i0 + wm * 32 + mt * 16 + gp;
        for (int nb = 0; nb < nBlk; nb++) {
            int col = (nbBase + nb) * 8 + tg * 2;
            size_t o0 = (size_t)row0 * STRIDE_OUT + col;
            size_t o1 = (size_t)(row0 + 8) * STRIDE_OUT + col;
            g_num[sp][o0]     = acc[mt][nb][0];
            g_num[sp][o0 + 1] = acc[mt][nb][1];
            g_num[sp][o1]     = acc[mt][nb][2];
            g_num[sp][o1 + 1] = acc[mt][nb][3];
        }
    }
}

// ---------------- kernel 4: combine splits, divide, ELU ----------------
__global__ void k_final(float* __restrict__ out) {
    int idx = blockIdx.x * 256 + threadIdx.x;
    int i = idx >> 6, c = idx & 63;
    size_t b = (size_t)i * STRIDE_OUT;
    float num = 0.f, den = 0.f;
    #pragma unroll
    for (int s2 = 0; s2 < KSPLIT; s2++) {
        num += g_num[s2][b + c];
        den += g_num[s2][b + 64];
    }
    float hv = num / den;
    out[idx] = hv > 0.f ? hv : expm1f(hv);
}

extern "C" void kernel_launch(void* const* d_in, const int* in_sizes, int n_in,
                              void* d_out, int out_size) {
    const float* x   = (const float*)d_in[0];
    const int*   adj = (const int*)  d_in[1];
    const float* W   = (const float*)d_in[2];
    const float* a   = (const float*)d_in[3];
    float* out = (float*)d_out;

    cudaFuncSetAttribute(k_main_tc, cudaFuncAttributeMaxDynamicSharedMemorySize, SM_TOTAL);

    k_gemm_h<<<NN/64, 256>>>(x, W, a);
    dim3 gt(NN/256, NB);
    k_tables<<<gt, 256>>>();
    dim3 gm(NN/MT, KSPLIT);
    k_main_tc<<<gm, 256, SM_TOTAL>>>(adj);
    k_final<<<(NN*FO)/256, 256>>>(out);
}